// round 13
// baseline (speedup 1.0000x reference)
#include <cuda_runtime.h>
#include <math_constants.h>

// KNN max-pooling: out[q, :] = max over j in 0..15 of feat[idx[q, j], :]
// feat: [100000, 64] f32, idx: [100000, 16] int32, out: [100000, 64] f32.
//
// 16 threads per query (2 queries/warp). Lane l owns channels [4l, 4l+4) as a
// float4. Neighbor row offsets broadcast via 32-bit shfl in the 16-lane
// segment; gathers are fully-coalesced 512 B per warp instruction.
//
// R10/R11 change (unmeasured in R11 due to broker failure; re-submitting):
// L1 BYPASS on the gather. Measured L1 hit rate for this random gather is ~1%
// (21.6K line draws/SM from a 200K-line universe, L1 holds 1.8K lines), yet
// every miss still allocated + filled the L1 data array -- ~2x data-path
// traversals per line, which accounts for the occupancy-invariant ~25us
// plateau (occ 42/64/88% all ~25-27us). ld.global.cg caches at L2 only:
// no L1 allocation, no fill wavefronts, loads still batchable (no volatile
// semantics, unlike .cv). feat stays L2-resident (25.6MB < 126MB).

#define NSAMPLE 16
#define C4 16  // 64 channels / 4 per float4

__device__ __forceinline__ float4 ldg_cg(const float4* p) {
    float4 v;
    asm("ld.global.cg.v4.f32 {%0,%1,%2,%3}, [%4];"
        : "=f"(v.x), "=f"(v.y), "=f"(v.z), "=f"(v.w)
        : "l"(p));
    return v;
}

__device__ __forceinline__ void fmax4(float4& a, const float4& b) {
    a.x = fmaxf(a.x, b.x);
    a.y = fmaxf(a.y, b.y);
    a.z = fmaxf(a.z, b.z);
    a.w = fmaxf(a.w, b.w);
}

__global__ void __launch_bounds__(256, 6) knn_pool_kernel(
    const float4* __restrict__ feat,   // [N, 16] float4
    const int* __restrict__ idx,       // [M, 16] int32
    float4* __restrict__ out,          // [M, 16] float4
    int M)
{
    int tid = blockIdx.x * blockDim.x + threadIdx.x;
    int q = tid >> 4;
    int lane = tid & 15;
    if (q >= M) return;

    // Coalesced idx load; pre-scale to float4 row offset (fits in 32 bits).
    int my_off = __ldg(&idx[q * NSAMPLE + lane]) * C4;

    float4 m;
    m.x = -CUDART_INF_F; m.y = -CUDART_INF_F;
    m.z = -CUDART_INF_F; m.w = -CUDART_INF_F;

    #pragma unroll
    for (int j = 0; j < NSAMPLE; ++j) {
        int nb = __shfl_sync(0xFFFFFFFFu, my_off, j, 16);
        float4 v = ldg_cg(&feat[nb + lane]);
        fmax4(m, v);
    }

    // Streaming store: output is write-once, don't displace feat in L2.
    __stcs(&out[q * C4 + lane], m);
}

extern "C" void kernel_launch(void* const* d_in, const int* in_sizes, int n_in,
                              void* d_out, int out_size)
{
    const float4* feat = (const float4*)d_in[0];
    const int* idx     = (const int*)d_in[1];
    float4* out        = (float4*)d_out;

    int M = in_sizes[1] / NSAMPLE;  // idx has M*16 elements

    int total_threads = M * 16;
    int block = 256;
    int grid = (total_threads + block - 1) / block;
    knn_pool_kernel<<<grid, block>>>(feat, idx, out, M);
}